// round 14
// baseline (speedup 1.0000x reference)
#include <cuda_runtime.h>
#include <cuda_bf16.h>
#include <cuda_fp16.h>
#include <math.h>
#include <stdint.h>

// Problem constants
#define B_    2
#define T_    2048
#define C_    768
#define H_    12
#define HD_   64
#define M_    4096
#define K_    768
#define N_QKV 2304

// ---------------------------------------------------------------------------
// Scratch (allocation-free: __device__ globals) — fp16 everywhere
// ---------------------------------------------------------------------------
__device__ alignas(16) __half g_qh[B_ * H_ * T_ * HD_];   // pre-scaled
__device__ alignas(16) __half g_kh[B_ * H_ * T_ * HD_];
__device__ alignas(16) __half g_vh[B_ * H_ * T_ * HD_];

__device__ alignas(16) __half g_xh[M_ * K_];
__device__ alignas(16) __half g_wa[N_QKV * K_];
__device__ alignas(16) __half g_wp[C_ * C_];
__device__ alignas(16) __half g_yh[M_ * C_];

// ---------------------------------------------------------------------------
// PTX helpers
// ---------------------------------------------------------------------------
__device__ __forceinline__ uint32_t smem_u32(const void* p) {
    uint32_t a;
    asm("{ .reg .u64 t; cvta.to.shared.u64 t, %1; cvt.u32.u64 %0, t; }" : "=r"(a) : "l"(p));
    return a;
}
__device__ __forceinline__ void ldsm_x4(uint32_t* r, uint32_t addr) {
    asm volatile("ldmatrix.sync.aligned.m8n8.x4.shared.b16 {%0,%1,%2,%3}, [%4];"
                 : "=r"(r[0]), "=r"(r[1]), "=r"(r[2]), "=r"(r[3]) : "r"(addr));
}
__device__ __forceinline__ void ldsm_x4_t(uint32_t* r, uint32_t addr) {
    asm volatile("ldmatrix.sync.aligned.m8n8.x4.trans.shared.b16 {%0,%1,%2,%3}, [%4];"
                 : "=r"(r[0]), "=r"(r[1]), "=r"(r[2]), "=r"(r[3]) : "r"(addr));
}
__device__ __forceinline__ void ldsm_x2(uint32_t* r, uint32_t addr) {
    asm volatile("ldmatrix.sync.aligned.m8n8.x2.shared.b16 {%0,%1}, [%2];"
                 : "=r"(r[0]), "=r"(r[1]) : "r"(addr));
}
__device__ __forceinline__ void mma16816h(float* c, const uint32_t* a, const uint32_t* b) {
    asm volatile("mma.sync.aligned.m16n8k16.row.col.f32.f16.f16.f32 "
                 "{%0,%1,%2,%3}, {%4,%5,%6,%7}, {%8,%9}, {%0,%1,%2,%3};"
                 : "+f"(c[0]), "+f"(c[1]), "+f"(c[2]), "+f"(c[3])
                 : "r"(a[0]), "r"(a[1]), "r"(a[2]), "r"(a[3]), "r"(b[0]), "r"(b[1]));
}
__device__ __forceinline__ float ex2f(float x) {
    float y; asm("ex2.approx.f32 %0, %1;" : "=f"(y) : "f"(x)); return y;
}
__device__ __forceinline__ uint32_t f2h2(float a, float b) {
    __half2 h = __floats2half2_rn(a, b);
    return *reinterpret_cast<uint32_t*>(&h);
}
__device__ __forceinline__ void redg_f32(float* p, float v) {
    asm volatile("red.global.add.f32 [%0], %1;" :: "l"(p), "f"(v) : "memory");
}
#define CP_ASYNC16(dst, src) \
    asm volatile("cp.async.cg.shared.global [%0], [%1], 16;" :: "r"(dst), "l"(src) : "memory")
#define CP_COMMIT() asm volatile("cp.async.commit_group;" ::: "memory")

// tail-aware wait: allow `pend` incomplete groups (0..7)
#define WAIT_PEND(pend) do {                                                     \
    int _p = (pend);                                                             \
    if (_p >= 7)      { asm volatile("cp.async.wait_group 7;" ::: "memory"); }   \
    else if (_p == 6) { asm volatile("cp.async.wait_group 6;" ::: "memory"); }   \
    else if (_p == 5) { asm volatile("cp.async.wait_group 5;" ::: "memory"); }   \
    else if (_p == 4) { asm volatile("cp.async.wait_group 4;" ::: "memory"); }   \
    else if (_p == 3) { asm volatile("cp.async.wait_group 3;" ::: "memory"); }   \
    else if (_p == 2) { asm volatile("cp.async.wait_group 2;" ::: "memory"); }   \
    else if (_p == 1) { asm volatile("cp.async.wait_group 1;" ::: "memory"); }   \
    else              { asm volatile("cp.async.wait_group 0;" ::: "memory"); }   \
} while (0)

#define SWZ64(o)  ((o) ^ (((o) >> 3) & 0x30))
#define SWZ128(o) ((o) ^ (((o) >> 3) & 0x70))

// ---------------------------------------------------------------------------
// Zero-init for the fp32 output (needed by split-K red.global epilogue)
// ---------------------------------------------------------------------------
__global__ __launch_bounds__(256) void zero_kernel(float4* __restrict__ out, int n4)
{
    int idx = blockIdx.x * blockDim.x + threadIdx.x;
    if (idx < n4) out[idx] = make_float4(0.f, 0.f, 0.f, 0.f);
}

// ---------------------------------------------------------------------------
// Conversion: x, wa, wp -> single fp16
// ---------------------------------------------------------------------------
__global__ __launch_bounds__(256) void convert_kernel(
    const float* __restrict__ x, const float* __restrict__ wa, const float* __restrict__ wp)
{
    const int nx = M_ * K_ / 4, na = N_QKV * K_ / 4, np = C_ * C_ / 4;
    int idx = blockIdx.x * blockDim.x + threadIdx.x;
    const float* src; __half* dst; int l;
    if (idx < nx)                { src = x;  dst = g_xh; l = idx; }
    else if (idx < nx + na)      { src = wa; dst = g_wa; l = idx - nx; }
    else if (idx < nx + na + np) { src = wp; dst = g_wp; l = idx - nx - na; }
    else return;

    float4 v = ((const float4*)src)[l];
    uint32_t h2[2] = { f2h2(v.x, v.y), f2h2(v.z, v.w) };
    ((uint2*)dst)[l] = *(uint2*)h2;
}

// ---------------------------------------------------------------------------
// Templated tensor-core GEMM: C[M,N] = A[M,K] @ Bw[N,K]^T, fp16 x fp16 (1 prod).
// MODE 0: A=g_xh, B=g_wa -> scatter q(scaled)/k/v fp16. KSPL=1.
// MODE 1: A=g_yh, B=g_wp -> fp32 Cout via red.global (KSPL=2 split-K).
// 6-stage ring, 2 CTA/SM.
// ---------------------------------------------------------------------------
#define BK      32
#define NIT     (K_ / BK)           // 24

template<int MT, int MODE, int KSPL>
__global__ __launch_bounds__(256, 2)
void tcgemm(float* __restrict__ Cout, const float* __restrict__ sp, int N)
{
    constexpr int TILE_A  = MT * 64;            // A tile bytes
    constexpr int TILE_Bb = 128 * 64;           // B tile bytes
    constexpr int STAGE   = TILE_A + TILE_Bb;
    constexpr int NST     = 6;
    constexpr int DEPTH   = NST - 1;
    constexpr int MI      = MT / 32;
    constexpr int NLOC    = NIT / KSPL;

    extern __shared__ char smem[];
    uint32_t sb = smem_u32(smem);

    const __half* Ah = (MODE == 0) ? g_xh : g_yh;
    const __half* Bw = (MODE == 0) ? g_wa : g_wp;

    float qsc = 1.0f;
    if (MODE == 0)
        qsc = sp[0] * (logf(2048.0f) * 0.125f) * 1.4426950408889634f;

    int tid = threadIdx.x;
    int lane = tid & 31;
    int wid = tid >> 5;
    int wm = wid >> 2;          // 0..1
    int wn = wid & 3;           // 0..3
    int m0 = blockIdx.y * MT;
    int n0 = blockIdx.x * 128;
    int kbase = blockIdx.z * NLOC * BK;

    auto issue = [&](int it) {
        uint32_t dst0 = sb + (it % NST) * STAGE;
        int k0 = kbase + it * BK;
#pragma unroll
        for (int j = 0; j < (MT * 4) / 256; j++) {
            int c = tid + j * 256;
            int row = c >> 2;
            int seg = c & 3;
            uint32_t doff = SWZ64((uint32_t)(row * 64 + seg * 16));
            CP_ASYNC16(dst0 + doff, Ah + (size_t)(m0 + row) * K_ + k0 + seg * 8);
        }
#pragma unroll
        for (int j = 0; j < 2; j++) {
            int c = tid + j * 256;
            int row = c >> 2;
            int seg = c & 3;
            uint32_t doff = SWZ64((uint32_t)(row * 64 + seg * 16));
            CP_ASYNC16(dst0 + TILE_A + doff, Bw + (size_t)(n0 + row) * K_ + k0 + seg * 8);
        }
        CP_COMMIT();
    };

    float acc[MI][4][4];
#pragma unroll
    for (int mi = 0; mi < MI; mi++)
#pragma unroll
        for (int ni = 0; ni < 4; ni++)
#pragma unroll
            for (int q = 0; q < 4; q++) acc[mi][ni][q] = 0.0f;

#pragma unroll
    for (int i = 0; i < DEPTH; i++)
        if (i < NLOC) issue(i);

    int a_rowsel = (lane & 15);
    int a_half   = (lane >> 4) * 16;
    int b_rowsel = (lane & 7);
    int b_half   = ((lane >> 3) & 1) * 16;

    for (int it = 0; it < NLOC; it++) {
        int pend = NLOC - 1 - it;
        if (pend > DEPTH - 1) pend = DEPTH - 1;
        WAIT_PEND(pend);
        __syncthreads();
        if (it + DEPTH < NLOC) issue(it + DEPTH);

        uint32_t s0 = sb + (it % NST) * STAGE;
#pragma unroll
        for (int ks = 0; ks < 2; ks++) {
            uint32_t af[MI][4], bf[4][2];
#pragma unroll
            for (int mi = 0; mi < MI; mi++) {
                uint32_t lofs = (uint32_t)((wm * (MT / 2) + mi * 16 + a_rowsel) * 64
                                           + ks * 32 + a_half);
                ldsm_x4(af[mi], s0 + SWZ64(lofs));
            }
#pragma unroll
            for (int ni = 0; ni < 4; ni++) {
                uint32_t lofs = (uint32_t)((wn * 32 + ni * 8 + b_rowsel) * 64
                                           + ks * 32 + b_half);
                ldsm_x2(bf[ni], s0 + TILE_A + SWZ64(lofs));
            }
#pragma unroll
            for (int mi = 0; mi < MI; mi++)
#pragma unroll
                for (int ni = 0; ni < 4; ni++)
                    mma16816h(acc[mi][ni], af[mi], bf[ni]);
        }
    }
    __syncthreads();

    // Epilogue: stage C tile in smem, coalesced write
    float* stage = (float*)smem;   // [MT][132]
    int rq  = lane >> 2;
    int cp2 = (lane & 3) * 2;
#pragma unroll
    for (int mi = 0; mi < MI; mi++)
#pragma unroll
        for (int ni = 0; ni < 4; ni++) {
            int r = wm * (MT / 2) + mi * 16 + rq;
            int c = wn * 32 + ni * 8 + cp2;
            stage[r * 132 + c]           = acc[mi][ni][0];
            stage[r * 132 + c + 1]       = acc[mi][ni][1];
            stage[(r + 8) * 132 + c]     = acc[mi][ni][2];
            stage[(r + 8) * 132 + c + 1] = acc[mi][ni][3];
        }
    __syncthreads();

    constexpr int TPR = 256 / MT;          // threads per row
    constexpr int CW  = 128 / TPR;         // floats per thread
    int r = tid / TPR;
    int part = tid % TPR;
    const float* sr = stage + r * 132 + part * CW;

    if (MODE == 0) {
        // qkv scatter: q (scaled) / k / v single fp16
        int n = n0 + part * CW;
        int pt = n / 768;
        int w = n - pt * 768;
        int h = w >> 6;
        int m = m0 + r;
        int b = m >> 11;
        int t = m & 2047;
        size_t base = (((size_t)(b * H_ + h)) * T_ + t) * HD_;
        float sc = (pt == 0) ? qsc : 1.0f;
        __half* dst = (pt == 0) ? g_qh : (pt == 1) ? g_kh : g_vh;
        uint32_t hw[CW / 2];
#pragma unroll
        for (int i = 0; i < CW / 2; i++)
            hw[i] = f2h2(sr[2 * i] * sc, sr[2 * i + 1] * sc);
        uint4* ph = (uint4*)(dst + base);
#pragma unroll
        for (int q = 0; q < CW / 8; q++) ph[q] = ((uint4*)hw)[q];
    } else {
        float* gp = Cout + (size_t)(m0 + r) * N + n0 + part * CW;
        if (KSPL == 1) {
#pragma unroll
            for (int q = 0; q < CW / 4; q++)
                ((float4*)gp)[q] = ((const float4*)sr)[q];
        } else {
#pragma unroll
            for (int q = 0; q < CW; q++)
                redg_f32(gp + q, sr[q]);
        }
    }
}

// ---------------------------------------------------------------------------
// MMA flash attention, block-causal (block = 64 = k-tile), no online max.
// S: Q fp16 x K fp16. PV: fp16 x fp16. 6-stage K/V ring, 2 CTA/SM.
// ---------------------------------------------------------------------------
#define KV_TILE  (64 * 128)          // 8192
#define ASTG     (2 * KV_TILE)       // 16384 : K,V
#define NAST     6
#define SM_ATT   (NAST * ASTG)       // 98304

__global__ __launch_bounds__(256, 2) void attn_mma()
{
    extern __shared__ char smem[];
    uint32_t sb = smem_u32(smem);
    int tid = threadIdx.x;
    int lane = tid & 31;
    int w = tid >> 5;

    int bh = blockIdx.x;
    int qt = 15 - blockIdx.y;

    const __half* Qh = g_qh + ((size_t)bh * T_ + qt * 128) * HD_;

    // ---- load Q tile, extract A-fragments ----
#pragma unroll
    for (int j = 0; j < 4; j++) {
        int idx = tid + j * 256;
        int row = idx >> 3;
        int seg = idx & 7;
        uint32_t doff = SWZ128((uint32_t)(row * 128 + seg * 16));
        size_t goff = (size_t)row * HD_ + seg * 8;
        CP_ASYNC16(sb + doff, Qh + goff);
    }
    CP_COMMIT();
    asm volatile("cp.async.wait_group 0;" ::: "memory");
    __syncthreads();

    uint32_t qh[4][4];
#pragma unroll
    for (int kb = 0; kb < 4; kb++) {
        uint32_t lofs = (uint32_t)((w * 16 + (lane & 15)) * 128 + kb * 32 + ((lane >> 4) & 1) * 16);
        ldsm_x4(qh[kb], sb + SWZ128(lofs));
    }
    __syncthreads();

    const __half* Kh = g_kh + (size_t)bh * T_ * HD_;
    const __half* Vh = g_vh + (size_t)bh * T_ * HD_;

    int nkt = 2 * qt + 2;
    int ktmax_w = 2 * qt + ((w >= 4) ? 1 : 0);

    auto issue = [&](int kt) {
        uint32_t d0 = sb + (kt % NAST) * ASTG;
        size_t g0 = (size_t)(kt * 64) * HD_;
#pragma unroll
        for (int j = 0; j < 2; j++) {
            int idx = tid + j * 256;
            int row = idx >> 3;
            int seg = idx & 7;
            uint32_t doff = SWZ128((uint32_t)(row * 128 + seg * 16));
            size_t goff = g0 + (size_t)row * HD_ + seg * 8;
            CP_ASYNC16(d0 + doff,           Kh + goff);
            CP_ASYNC16(d0 + KV_TILE + doff, Vh + goff);
        }
        CP_COMMIT();
    };

#pragma unroll
    for (int i = 0; i < 5; i++)
        if (i < nkt) issue(i);

    float oacc[8][4];
#pragma unroll
    for (int j = 0; j < 8; j++)
#pragma unroll
        for (int q = 0; q < 4; q++) oacc[j][q] = 0.0f;
    float l0 = 0.0f, l1 = 0.0f;

    for (int kt = 0; kt < nkt; kt++) {
        int pend = nkt - 1 - kt;
        if (pend > 4) pend = 4;
        WAIT_PEND(pend);
        __syncthreads();
        if (kt + 5 < nkt) issue(kt + 5);

        if (kt <= ktmax_w) {
            uint32_t base = sb + (kt % NAST) * ASTG;

            // ---- S = Q @ K^T ----
            float sacc[8][4];
#pragma unroll
            for (int j = 0; j < 8; j++)
#pragma unroll
                for (int q = 0; q < 4; q++) sacc[j][q] = 0.0f;

#pragma unroll
            for (int jj = 0; jj < 4; jj++) {
#pragma unroll
                for (int kb = 0; kb < 4; kb++) {
                    uint32_t khf[4];
                    uint32_t lofs = (uint32_t)(
                        (jj * 16 + (lane & 7) + ((lane >> 4) & 1) * 8) * 128
                        + kb * 32 + ((lane >> 3) & 1) * 16);
                    ldsm_x4(khf, base + SWZ128(lofs));
                    mma16816h(sacc[2 * jj],     qh[kb], khf + 0);
                    mma16816h(sacc[2 * jj + 1], qh[kb], khf + 2);
                }
            }

            // ---- p = exp2(S), accumulate partial row sums ----
#pragma unroll
            for (int j = 0; j < 8; j++) {
                sacc[j][0] = ex2f(sacc[j][0]);
                sacc[j][1] = ex2f(sacc[j][1]);
                sacc[j][2] = ex2f(sacc[j][2]);
                sacc[j][3] = ex2f(sacc[j][3]);
                l0 += sacc[j][0] + sacc[j][1];
                l1 += sacc[j][2] + sacc[j][3];
            }

            // ---- O += P @ V ----
#pragma unroll
            for (int kb = 0; kb < 4; kb++) {
                uint32_t pa[4];
                int j0 = 2 * kb, j1 = 2 * kb + 1;
                pa[0] = f2h2(sacc[j0][0], sacc[j0][1]);
                pa[1] = f2h2(sacc[j0][2], sacc[j0][3]);
                pa[2] = f2h2(sacc[j1][0], sacc[j1][1]);
                pa[3] = f2h2(sacc[j1][2], sacc[j1][3]);
#pragma unroll
                for (int dd = 0; dd < 4; dd++) {
                    uint32_t vhf[4];
                    uint32_t lofs = (uint32_t)(
                        (kb * 16 + (lane & 15)) * 128
                        + dd * 32 + ((lane >> 4) & 1) * 16);
                    ldsm_x4_t(vhf, base + KV_TILE + SWZ128(lofs));
                    mma16816h(oacc[2 * dd],     pa, vhf + 0);
                    mma16816h(oacc[2 * dd + 1], pa, vhf + 2);
                }
            }
        }
    }
    // deferred row-sum reduction (lanes xor 1,2 share the row)
    l0 += __shfl_xor_sync(0xffffffffu, l0, 1);
    l0 += __shfl_xor_sync(0xffffffffu, l0, 2);
    l1 += __shfl_xor_sync(0xffffffffu, l1, 1);
    l1 += __shfl_xor_sync(0xffffffffu, l1, 2);
    __syncthreads();

    // ---- epilogue: normalize, stage, write y single fp16 ----
    float inv0 = 1.0f / l0, inv1 = 1.0f / l1;
    float* st = (float*)smem;                 // [128][68]
    int r0 = w * 16 + (lane >> 2);
    int cb = (lane & 3) * 2;
#pragma unroll
    for (int j = 0; j < 8; j++) {
        st[r0 * 68 + j * 8 + cb]           = oacc[j][0] * inv0;
        st[r0 * 68 + j * 8 + cb + 1]       = oacc[j][1] * inv0;
        st[(r0 + 8) * 68 + j * 8 + cb]     = oacc[j][2] * inv1;
        st[(r0 + 8) * 68 + j * 8 + cb + 1] = oacc[j][3] * inv1;
    }
    __syncthreads();

    int row = tid >> 1;
    int hf = tid & 1;
    int b = bh / H_;
    int h = bh - b * H_;
    int t = qt * 128 + row;
    size_t ybase = ((size_t)(b * T_ + t)) * C_ + h * HD_ + hf * 32;
    const float* srow = st + row * 68 + hf * 32;
    uint32_t hw[16];
#pragma unroll
    for (int i = 0; i < 16; i++)
        hw[i] = f2h2(srow[2 * i], srow[2 * i + 1]);
    uint4* ph = (uint4*)(g_yh + ybase);
#pragma unroll
    for (int q = 0; q < 4; q++) ph[q] = ((uint4*)hw)[q];
}

// ---------------------------------------------------------------------------
extern "C" void kernel_launch(void* const* d_in, const int* in_sizes, int n_in,
                              void* d_out, int out_size)
{
    const float* x     = (const float*)d_in[0];
    const float* wattn = (const float*)d_in[1];
    const float* wproj = (const float*)d_in[2];
    const float* s     = (const float*)d_in[3];
    float* out = (float*)d_out;

    // 0a) zero the fp32 output (split-K epilogue accumulates into it)
    int n4 = M_ * C_ / 4;
    zero_kernel<<<(n4 + 255) / 256, 256>>>((float4*)out, n4);

    // 0b) x, weights -> single fp16
    int tot4 = (M_ * K_ + N_QKV * K_ + C_ * C_) / 4;
    convert_kernel<<<(tot4 + 255) / 256, 256>>>(x, wattn, wproj);

    const int SM_G = 6 * (128 * 64 + 128 * 64);   // 98304
    cudaFuncSetAttribute((const void*)tcgemm<128, 0, 1>,
                         cudaFuncAttributeMaxDynamicSharedMemorySize, SM_G);
    cudaFuncSetAttribute((const void*)tcgemm<128, 1, 2>,
                         cudaFuncAttributeMaxDynamicSharedMemorySize, SM_G);
    cudaFuncSetAttribute((const void*)attn_mma,
                         cudaFuncAttributeMaxDynamicSharedMemorySize, SM_ATT);

    // 1) qkv projection (1-product fp16): q (pre-scaled) / k / v fp16
    tcgemm<128, 0, 1><<<dim3(N_QKV / 128, M_ / 128, 1), 256, SM_G>>>(nullptr, s, N_QKV);

    // 2) MMA flash attention (writes y single fp16)
    attn_mma<<<dim3(B_ * H_, T_ / 128), 256, SM_ATT>>>();

    // 3) output projection: 128x128 tiles, split-K=2 (384 CTAs), red.global
    tcgemm<128, 1, 2><<<dim3(C_ / 128, M_ / 128, 2), 256, SM_G>>>(out, nullptr, C_);
}

// round 15
// speedup vs baseline: 1.2242x; 1.2242x over previous
#include <cuda_runtime.h>
#include <cuda_bf16.h>
#include <cuda_fp16.h>
#include <math.h>
#include <stdint.h>

// Problem constants
#define B_    2
#define T_    2048
#define C_    768
#define H_    12
#define HD_   64
#define M_    4096
#define K_    768
#define N_QKV 2304

// ---------------------------------------------------------------------------
// Scratch (allocation-free: __device__ globals) — fp16 everywhere
// ---------------------------------------------------------------------------
__device__ alignas(16) __half g_qh[B_ * H_ * T_ * HD_];   // pre-scaled
__device__ alignas(16) __half g_kh[B_ * H_ * T_ * HD_];
__device__ alignas(16) __half g_vh[B_ * H_ * T_ * HD_];

__device__ alignas(16) __half g_xh[M_ * K_];
__device__ alignas(16) __half g_wa[N_QKV * K_];
__device__ alignas(16) __half g_wp[C_ * C_];
__device__ alignas(16) __half g_yh[M_ * C_];

// ---------------------------------------------------------------------------
// PTX helpers
// ---------------------------------------------------------------------------
__device__ __forceinline__ uint32_t smem_u32(const void* p) {
    uint32_t a;
    asm("{ .reg .u64 t; cvta.to.shared.u64 t, %1; cvt.u32.u64 %0, t; }" : "=r"(a) : "l"(p));
    return a;
}
__device__ __forceinline__ void ldsm_x4(uint32_t* r, uint32_t addr) {
    asm volatile("ldmatrix.sync.aligned.m8n8.x4.shared.b16 {%0,%1,%2,%3}, [%4];"
                 : "=r"(r[0]), "=r"(r[1]), "=r"(r[2]), "=r"(r[3]) : "r"(addr));
}
__device__ __forceinline__ void ldsm_x4_t(uint32_t* r, uint32_t addr) {
    asm volatile("ldmatrix.sync.aligned.m8n8.x4.trans.shared.b16 {%0,%1,%2,%3}, [%4];"
                 : "=r"(r[0]), "=r"(r[1]), "=r"(r[2]), "=r"(r[3]) : "r"(addr));
}
__device__ __forceinline__ void ldsm_x2(uint32_t* r, uint32_t addr) {
    asm volatile("ldmatrix.sync.aligned.m8n8.x2.shared.b16 {%0,%1}, [%2];"
                 : "=r"(r[0]), "=r"(r[1]) : "r"(addr));
}
__device__ __forceinline__ void mma16816h(float* c, const uint32_t* a, const uint32_t* b) {
    asm volatile("mma.sync.aligned.m16n8k16.row.col.f32.f16.f16.f32 "
                 "{%0,%1,%2,%3}, {%4,%5,%6,%7}, {%8,%9}, {%0,%1,%2,%3};"
                 : "+f"(c[0]), "+f"(c[1]), "+f"(c[2]), "+f"(c[3])
                 : "r"(a[0]), "r"(a[1]), "r"(a[2]), "r"(a[3]), "r"(b[0]), "r"(b[1]));
}
__device__ __forceinline__ float ex2f(float x) {
    float y; asm("ex2.approx.f32 %0, %1;" : "=f"(y) : "f"(x)); return y;
}
__device__ __forceinline__ uint32_t f2h2(float a, float b) {
    __half2 h = __floats2half2_rn(a, b);
    return *reinterpret_cast<uint32_t*>(&h);
}
#define CP_ASYNC16(dst, src) \
    asm volatile("cp.async.cg.shared.global [%0], [%1], 16;" :: "r"(dst), "l"(src) : "memory")
#define CP_COMMIT() asm volatile("cp.async.commit_group;" ::: "memory")
#define CP_WAIT(n)  asm volatile("cp.async.wait_group %0;" :: "n"(n) : "memory")

#define SWZ64(o)  ((o) ^ (((o) >> 3) & 0x30))
#define SWZ128(o) ((o) ^ (((o) >> 3) & 0x70))

// ---------------------------------------------------------------------------
// Conversion: x, wa, wp -> single fp16
// ---------------------------------------------------------------------------
__global__ __launch_bounds__(256) void convert_kernel(
    const float* __restrict__ x, const float* __restrict__ wa, const float* __restrict__ wp)
{
    const int nx = M_ * K_ / 4, na = N_QKV * K_ / 4, np = C_ * C_ / 4;
    int idx = blockIdx.x * blockDim.x + threadIdx.x;
    const float* src; __half* dst; int l;
    if (idx < nx)                { src = x;  dst = g_xh; l = idx; }
    else if (idx < nx + na)      { src = wa; dst = g_wa; l = idx - nx; }
    else if (idx < nx + na + np) { src = wp; dst = g_wp; l = idx - nx - na; }
    else return;

    float4 v = ((const float4*)src)[l];
    uint32_t h2[2] = { f2h2(v.x, v.y), f2h2(v.z, v.w) };
    ((uint2*)dst)[l] = *(uint2*)h2;
}

// ---------------------------------------------------------------------------
// Templated tensor-core GEMM: C[M,N] = A[M,K] @ Bw[N,K]^T, fp16 x fp16 (1 prod).
// MODE 0: MT=128, A=g_xh, B=g_wa -> scatter q(scaled)/k/v fp16, 6-stage ring.
// MODE 1: MT=64,  A=g_yh, B=g_wp -> fp32 row-major Cout, 8-stage ring.
// Constant-depth waits (empty commits in tail). 2 CTA/SM.
// ---------------------------------------------------------------------------
#define BK      32
#define NIT     (K_ / BK)           // 24

template<int MT, int MODE>
__global__ __launch_bounds__(256, 2)
void tcgemm(float* __restrict__ Cout, const float* __restrict__ sp, int N)
{
    constexpr int TILE_A  = MT * 64;            // A tile bytes
    constexpr int TILE_Bb = 128 * 64;           // B tile bytes
    constexpr int STAGE   = TILE_A + TILE_Bb;
    constexpr int NST     = (MT == 128) ? 6 : 8;
    constexpr int DEPTH   = NST - 1;
    constexpr int MI      = MT / 32;

    extern __shared__ char smem[];
    uint32_t sb = smem_u32(smem);

    const __half* Ah = (MODE == 0) ? g_xh : g_yh;
    const __half* Bw = (MODE == 0) ? g_wa : g_wp;

    float qsc = 1.0f;
    if (MODE == 0)
        qsc = sp[0] * (logf(2048.0f) * 0.125f) * 1.4426950408889634f;

    int tid = threadIdx.x;
    int lane = tid & 31;
    int wid = tid >> 5;
    int wm = wid >> 2;          // 0..1
    int wn = wid & 3;           // 0..3
    int m0 = blockIdx.y * MT;
    int n0 = blockIdx.x * 128;

    auto issue = [&](int it) {
        uint32_t dst0 = sb + (it % NST) * STAGE;
        int k0 = it * BK;
#pragma unroll
        for (int j = 0; j < (MT * 4) / 256; j++) {
            int c = tid + j * 256;
            int row = c >> 2;
            int seg = c & 3;
            uint32_t doff = SWZ64((uint32_t)(row * 64 + seg * 16));
            CP_ASYNC16(dst0 + doff, Ah + (size_t)(m0 + row) * K_ + k0 + seg * 8);
        }
#pragma unroll
        for (int j = 0; j < 2; j++) {
            int c = tid + j * 256;
            int row = c >> 2;
            int seg = c & 3;
            uint32_t doff = SWZ64((uint32_t)(row * 64 + seg * 16));
            CP_ASYNC16(dst0 + TILE_A + doff, Bw + (size_t)(n0 + row) * K_ + k0 + seg * 8);
        }
        CP_COMMIT();
    };

    float acc[MI][4][4];
#pragma unroll
    for (int mi = 0; mi < MI; mi++)
#pragma unroll
        for (int ni = 0; ni < 4; ni++)
#pragma unroll
            for (int q = 0; q < 4; q++) acc[mi][ni][q] = 0.0f;

#pragma unroll
    for (int i = 0; i < DEPTH; i++) issue(i);   // NIT=24 > DEPTH always

    int a_rowsel = (lane & 15);
    int a_half   = (lane >> 4) * 16;
    int b_rowsel = (lane & 7);
    int b_half   = ((lane >> 3) & 1) * 16;

    for (int it = 0; it < NIT; it++) {
        CP_WAIT(DEPTH - 1);                     // constant literal, no branches
        __syncthreads();
        if (it + DEPTH < NIT) issue(it + DEPTH);
        else                  CP_COMMIT();      // empty group keeps count exact

        uint32_t s0 = sb + (it % NST) * STAGE;
#pragma unroll
        for (int ks = 0; ks < 2; ks++) {
            uint32_t af[MI][4], bf[4][2];
#pragma unroll
            for (int mi = 0; mi < MI; mi++) {
                uint32_t lofs = (uint32_t)((wm * (MT / 2) + mi * 16 + a_rowsel) * 64
                                           + ks * 32 + a_half);
                ldsm_x4(af[mi], s0 + SWZ64(lofs));
            }
#pragma unroll
            for (int ni = 0; ni < 4; ni++) {
                uint32_t lofs = (uint32_t)((wn * 32 + ni * 8 + b_rowsel) * 64
                                           + ks * 32 + b_half);
                ldsm_x2(bf[ni], s0 + TILE_A + SWZ64(lofs));
            }
#pragma unroll
            for (int mi = 0; mi < MI; mi++)
#pragma unroll
                for (int ni = 0; ni < 4; ni++)
                    mma16816h(acc[mi][ni], af[mi], bf[ni]);
        }
    }
    __syncthreads();

    // Epilogue: stage C tile in smem, coalesced write
    float* stage = (float*)smem;   // [MT][132]
    int rq  = lane >> 2;
    int cp2 = (lane & 3) * 2;
#pragma unroll
    for (int mi = 0; mi < MI; mi++)
#pragma unroll
        for (int ni = 0; ni < 4; ni++) {
            int r = wm * (MT / 2) + mi * 16 + rq;
            int c = wn * 32 + ni * 8 + cp2;
            stage[r * 132 + c]           = acc[mi][ni][0];
            stage[r * 132 + c + 1]       = acc[mi][ni][1];
            stage[(r + 8) * 132 + c]     = acc[mi][ni][2];
            stage[(r + 8) * 132 + c + 1] = acc[mi][ni][3];
        }
    __syncthreads();

    constexpr int TPR = 256 / MT;          // threads per row (2 or 4)
    constexpr int CW  = 128 / TPR;         // floats per thread (64 or 32)
    int r = tid / TPR;
    int part = tid % TPR;
    const float* sr = stage + r * 132 + part * CW;

    if (MODE == 0) {
        // qkv scatter: q (scaled) / k / v single fp16
        int n = n0 + part * CW;
        int pt = n / 768;
        int w = n - pt * 768;
        int h = w >> 6;
        int m = m0 + r;
        int b = m >> 11;
        int t = m & 2047;
        size_t base = (((size_t)(b * H_ + h)) * T_ + t) * HD_;
        float sc = (pt == 0) ? qsc : 1.0f;
        __half* dst = (pt == 0) ? g_qh : (pt == 1) ? g_kh : g_vh;
        uint32_t hw[CW / 2];
#pragma unroll
        for (int i = 0; i < CW / 2; i++)
            hw[i] = f2h2(sr[2 * i] * sc, sr[2 * i + 1] * sc);
        uint4* ph = (uint4*)(dst + base);
#pragma unroll
        for (int q = 0; q < CW / 8; q++) ph[q] = ((uint4*)hw)[q];
    } else {
        float4* gp = (float4*)(Cout + (size_t)(m0 + r) * N + n0 + part * CW);
#pragma unroll
        for (int q = 0; q < CW / 4; q++) gp[q] = ((const float4*)sr)[q];
    }
}

// ---------------------------------------------------------------------------
// MMA flash attention, block-causal (block = 64 = k-tile), no online max.
// S: Q fp16 x K fp16. PV: fp16 x fp16. 6-stage K/V ring (constant-depth
// waits; short pipelines padded with empty commits). 2 CTA/SM.
// ---------------------------------------------------------------------------
#define KV_TILE  (64 * 128)          // 8192
#define ASTG     (2 * KV_TILE)       // 16384 : K,V
#define NAST     6
#define ADEPTH   5
#define SM_ATT   (NAST * ASTG)       // 98304

__global__ __launch_bounds__(256, 2) void attn_mma()
{
    extern __shared__ char smem[];
    uint32_t sb = smem_u32(smem);
    int tid = threadIdx.x;
    int lane = tid & 31;
    int w = tid >> 5;

    int bh = blockIdx.x;
    int qt = 15 - blockIdx.y;

    const __half* Qh = g_qh + ((size_t)bh * T_ + qt * 128) * HD_;

    // ---- load Q tile, extract A-fragments ----
#pragma unroll
    for (int j = 0; j < 4; j++) {
        int idx = tid + j * 256;
        int row = idx >> 3;
        int seg = idx & 7;
        uint32_t doff = SWZ128((uint32_t)(row * 128 + seg * 16));
        size_t goff = (size_t)row * HD_ + seg * 8;
        CP_ASYNC16(sb + doff, Qh + goff);
    }
    CP_COMMIT();
    CP_WAIT(0);
    __syncthreads();

    uint32_t qh[4][4];
#pragma unroll
    for (int kb = 0; kb < 4; kb++) {
        uint32_t lofs = (uint32_t)((w * 16 + (lane & 15)) * 128 + kb * 32 + ((lane >> 4) & 1) * 16);
        ldsm_x4(qh[kb], sb + SWZ128(lofs));
    }
    __syncthreads();

    const __half* Kh = g_kh + (size_t)bh * T_ * HD_;
    const __half* Vh = g_vh + (size_t)bh * T_ * HD_;

    int nkt = 2 * qt + 2;
    int ktmax_w = 2 * qt + ((w >= 4) ? 1 : 0);

    auto issue = [&](int kt) {
        uint32_t d0 = sb + (kt % NAST) * ASTG;
        size_t g0 = (size_t)(kt * 64) * HD_;
#pragma unroll
        for (int j = 0; j < 2; j++) {
            int idx = tid + j * 256;
            int row = idx >> 3;
            int seg = idx & 7;
            uint32_t doff = SWZ128((uint32_t)(row * 128 + seg * 16));
            size_t goff = g0 + (size_t)row * HD_ + seg * 8;
            CP_ASYNC16(d0 + doff,           Kh + goff);
            CP_ASYNC16(d0 + KV_TILE + doff, Vh + goff);
        }
        CP_COMMIT();
    };

    // prologue: always ADEPTH commits (empty beyond nkt) so the constant
    // wait depth below is exact for any nkt
#pragma unroll
    for (int i = 0; i < ADEPTH; i++) {
        if (i < nkt) issue(i);
        else         CP_COMMIT();
    }

    float oacc[8][4];
#pragma unroll
    for (int j = 0; j < 8; j++)
#pragma unroll
        for (int q = 0; q < 4; q++) oacc[j][q] = 0.0f;
    float l0 = 0.0f, l1 = 0.0f;

    for (int kt = 0; kt < nkt; kt++) {
        CP_WAIT(ADEPTH - 1);                 // constant literal
        __syncthreads();
        if (kt + ADEPTH < nkt) issue(kt + ADEPTH);
        else                   CP_COMMIT();

        if (kt <= ktmax_w) {
            uint32_t base = sb + (kt % NAST) * ASTG;

            // ---- S = Q @ K^T ----
            float sacc[8][4];
#pragma unroll
            for (int j = 0; j < 8; j++)
#pragma unroll
                for (int q = 0; q < 4; q++) sacc[j][q] = 0.0f;

#pragma unroll
            for (int jj = 0; jj < 4; jj++) {
#pragma unroll
                for (int kb = 0; kb < 4; kb++) {
                    uint32_t khf[4];
                    uint32_t lofs = (uint32_t)(
                        (jj * 16 + (lane & 7) + ((lane >> 4) & 1) * 8) * 128
                        + kb * 32 + ((lane >> 3) & 1) * 16);
                    ldsm_x4(khf, base + SWZ128(lofs));
                    mma16816h(sacc[2 * jj],     qh[kb], khf + 0);
                    mma16816h(sacc[2 * jj + 1], qh[kb], khf + 2);
                }
            }

            // ---- p = exp2(S), accumulate partial row sums ----
#pragma unroll
            for (int j = 0; j < 8; j++) {
                sacc[j][0] = ex2f(sacc[j][0]);
                sacc[j][1] = ex2f(sacc[j][1]);
                sacc[j][2] = ex2f(sacc[j][2]);
                sacc[j][3] = ex2f(sacc[j][3]);
                l0 += sacc[j][0] + sacc[j][1];
                l1 += sacc[j][2] + sacc[j][3];
            }

            // ---- O += P @ V ----
#pragma unroll
            for (int kb = 0; kb < 4; kb++) {
                uint32_t pa[4];
                int j0 = 2 * kb, j1 = 2 * kb + 1;
                pa[0] = f2h2(sacc[j0][0], sacc[j0][1]);
                pa[1] = f2h2(sacc[j0][2], sacc[j0][3]);
                pa[2] = f2h2(sacc[j1][0], sacc[j1][1]);
                pa[3] = f2h2(sacc[j1][2], sacc[j1][3]);
#pragma unroll
                for (int dd = 0; dd < 4; dd++) {
                    uint32_t vhf[4];
                    uint32_t lofs = (uint32_t)(
                        (kb * 16 + (lane & 15)) * 128
                        + dd * 32 + ((lane >> 4) & 1) * 16);
                    ldsm_x4_t(vhf, base + KV_TILE + SWZ128(lofs));
                    mma16816h(oacc[2 * dd],     pa, vhf + 0);
                    mma16816h(oacc[2 * dd + 1], pa, vhf + 2);
                }
            }
        }
    }
    // deferred row-sum reduction (lanes xor 1,2 share the row)
    l0 += __shfl_xor_sync(0xffffffffu, l0, 1);
    l0 += __shfl_xor_sync(0xffffffffu, l0, 2);
    l1 += __shfl_xor_sync(0xffffffffu, l1, 1);
    l1 += __shfl_xor_sync(0xffffffffu, l1, 2);
    __syncthreads();

    // ---- epilogue: normalize, stage, write y single fp16 ----
    float inv0 = 1.0f / l0, inv1 = 1.0f / l1;
    float* st = (float*)smem;                 // [128][68]
    int r0 = w * 16 + (lane >> 2);
    int cb = (lane & 3) * 2;
#pragma unroll
    for (int j = 0; j < 8; j++) {
        st[r0 * 68 + j * 8 + cb]           = oacc[j][0] * inv0;
        st[r0 * 68 + j * 8 + cb + 1]       = oacc[j][1] * inv0;
        st[(r0 + 8) * 68 + j * 8 + cb]     = oacc[j][2] * inv1;
        st[(r0 + 8) * 68 + j * 8 + cb + 1] = oacc[j][3] * inv1;
    }
    __syncthreads();

    int row = tid >> 1;
    int hf = tid & 1;
    int b = bh / H_;
    int h = bh - b * H_;
    int t = qt * 128 + row;
    size_t ybase = ((size_t)(b * T_ + t)) * C_ + h * HD_ + hf * 32;
    const float* srow = st + row * 68 + hf * 32;
    uint32_t hw[16];
#pragma unroll
    for (int i = 0; i < 16; i++)
        hw[i] = f2h2(srow[2 * i], srow[2 * i + 1]);
    uint4* ph = (uint4*)(g_yh + ybase);
#pragma unroll
    for (int q = 0; q < 4; q++) ph[q] = ((uint4*)hw)[q];
}

// ---------------------------------------------------------------------------
extern "C" void kernel_launch(void* const* d_in, const int* in_sizes, int n_in,
                              void* d_out, int out_size)
{
    const float* x     = (const float*)d_in[0];
    const float* wattn = (const float*)d_in[1];
    const float* wproj = (const float*)d_in[2];
    const float* s     = (const float*)d_in[3];
    float* out = (float*)d_out;

    // 0) x, weights -> single fp16
    int tot4 = (M_ * K_ + N_QKV * K_ + C_ * C_) / 4;
    convert_kernel<<<(tot4 + 255) / 256, 256>>>(x, wattn, wproj);

    const int SM_G0 = 6 * (128 * 64 + 128 * 64);   // 98304
    const int SM_G1 = 8 * (64 * 64 + 128 * 64);    // 98304
    cudaFuncSetAttribute((const void*)tcgemm<128, 0>,
                         cudaFuncAttributeMaxDynamicSharedMemorySize, SM_G0);
    cudaFuncSetAttribute((const void*)tcgemm<64, 1>,
                         cudaFuncAttributeMaxDynamicSharedMemorySize, SM_G1);
    cudaFuncSetAttribute((const void*)attn_mma,
                         cudaFuncAttributeMaxDynamicSharedMemorySize, SM_ATT);

    // 1) qkv projection (1-product fp16): q (pre-scaled) / k / v fp16
    tcgemm<128, 0><<<dim3(N_QKV / 128, M_ / 128), 256, SM_G0>>>(nullptr, s, N_QKV);

    // 2) MMA flash attention (writes y single fp16)
    attn_mma<<<dim3(B_ * H_, T_ / 128), 256, SM_ATT>>>();

    // 3) output projection (1-product, 64-row tiles, 8-stage ring)
    tcgemm<64, 1><<<dim3(C_ / 128, M_ / 64), 256, SM_G1>>>(out, nullptr, C_);
}

// round 16
// speedup vs baseline: 1.2263x; 1.0017x over previous
#include <cuda_runtime.h>
#include <cuda_bf16.h>
#include <cuda_fp16.h>
#include <math.h>
#include <stdint.h>

// Problem constants
#define B_    2
#define T_    2048
#define C_    768
#define H_    12
#define HD_   64
#define M_    4096
#define K_    768
#define N_QKV 2304

// ---------------------------------------------------------------------------
// Scratch (allocation-free: __device__ globals) — fp16 everywhere
// ---------------------------------------------------------------------------
__device__ alignas(16) __half g_qh[B_ * H_ * T_ * HD_];   // pre-scaled
__device__ alignas(16) __half g_kh[B_ * H_ * T_ * HD_];
__device__ alignas(16) __half g_vh[B_ * H_ * T_ * HD_];

__device__ alignas(16) __half g_xh[M_ * K_];
__device__ alignas(16) __half g_wa[N_QKV * K_];
__device__ alignas(16) __half g_wp[C_ * C_];
__device__ alignas(16) __half g_yh[M_ * C_];

// ---------------------------------------------------------------------------
// PTX helpers
// ---------------------------------------------------------------------------
__device__ __forceinline__ uint32_t smem_u32(const void* p) {
    uint32_t a;
    asm("{ .reg .u64 t; cvta.to.shared.u64 t, %1; cvt.u32.u64 %0, t; }" : "=r"(a) : "l"(p));
    return a;
}
__device__ __forceinline__ void ldsm_x4(uint32_t* r, uint32_t addr) {
    asm volatile("ldmatrix.sync.aligned.m8n8.x4.shared.b16 {%0,%1,%2,%3}, [%4];"
                 : "=r"(r[0]), "=r"(r[1]), "=r"(r[2]), "=r"(r[3]) : "r"(addr));
}
__device__ __forceinline__ void ldsm_x4_t(uint32_t* r, uint32_t addr) {
    asm volatile("ldmatrix.sync.aligned.m8n8.x4.trans.shared.b16 {%0,%1,%2,%3}, [%4];"
                 : "=r"(r[0]), "=r"(r[1]), "=r"(r[2]), "=r"(r[3]) : "r"(addr));
}
__device__ __forceinline__ void ldsm_x2(uint32_t* r, uint32_t addr) {
    asm volatile("ldmatrix.sync.aligned.m8n8.x2.shared.b16 {%0,%1}, [%2];"
                 : "=r"(r[0]), "=r"(r[1]) : "r"(addr));
}
__device__ __forceinline__ void mma16816h(float* c, const uint32_t* a, const uint32_t* b) {
    asm volatile("mma.sync.aligned.m16n8k16.row.col.f32.f16.f16.f32 "
                 "{%0,%1,%2,%3}, {%4,%5,%6,%7}, {%8,%9}, {%0,%1,%2,%3};"
                 : "+f"(c[0]), "+f"(c[1]), "+f"(c[2]), "+f"(c[3])
                 : "r"(a[0]), "r"(a[1]), "r"(a[2]), "r"(a[3]), "r"(b[0]), "r"(b[1]));
}
__device__ __forceinline__ float ex2f(float x) {
    float y; asm("ex2.approx.f32 %0, %1;" : "=f"(y) : "f"(x)); return y;
}
__device__ __forceinline__ uint32_t f2h2(float a, float b) {
    __half2 h = __floats2half2_rn(a, b);
    return *reinterpret_cast<uint32_t*>(&h);
}
#define CP_ASYNC16(dst, src) \
    asm volatile("cp.async.cg.shared.global [%0], [%1], 16;" :: "r"(dst), "l"(src) : "memory")
#define CP_COMMIT() asm volatile("cp.async.commit_group;" ::: "memory")
#define CP_WAIT(n)  asm volatile("cp.async.wait_group %0;" :: "n"(n) : "memory")

#define SWZ64(o)  ((o) ^ (((o) >> 3) & 0x30))
#define SWZ128(o) ((o) ^ (((o) >> 3) & 0x70))

// ---------------------------------------------------------------------------
// Conversion: x, wa, wp -> single fp16
// ---------------------------------------------------------------------------
__global__ __launch_bounds__(256) void convert_kernel(
    const float* __restrict__ x, const float* __restrict__ wa, const float* __restrict__ wp)
{
    const int nx = M_ * K_ / 4, na = N_QKV * K_ / 4, np = C_ * C_ / 4;
    int idx = blockIdx.x * blockDim.x + threadIdx.x;
    const float* src; __half* dst; int l;
    if (idx < nx)                { src = x;  dst = g_xh; l = idx; }
    else if (idx < nx + na)      { src = wa; dst = g_wa; l = idx - nx; }
    else if (idx < nx + na + np) { src = wp; dst = g_wp; l = idx - nx - na; }
    else return;

    float4 v = ((const float4*)src)[l];
    uint32_t h2[2] = { f2h2(v.x, v.y), f2h2(v.z, v.w) };
    ((uint2*)dst)[l] = *(uint2*)h2;
}

// ---------------------------------------------------------------------------
// Templated tensor-core GEMM: C[M,N] = A[M,K] @ Bw[N,K]^T, fp16 x fp16 (1 prod).
// MODE 0: MT=128, A=g_xh, B=g_wa -> scatter q(scaled)/k/v fp16, 6-stage ring.
// MODE 1: MT=64,  A=g_yh, B=g_wp -> fp32 row-major Cout, 8-stage ring.
// Constant-depth waits (empty commits in tail). 2 CTA/SM.
// ---------------------------------------------------------------------------
#define BK      32
#define NIT     (K_ / BK)           // 24

template<int MT, int MODE>
__global__ __launch_bounds__(256, 2)
void tcgemm(float* __restrict__ Cout, const float* __restrict__ sp, int N)
{
    constexpr int TILE_A  = MT * 64;            // A tile bytes
    constexpr int TILE_Bb = 128 * 64;           // B tile bytes
    constexpr int STAGE   = TILE_A + TILE_Bb;
    constexpr int NST     = (MT == 128) ? 6 : 8;
    constexpr int DEPTH   = NST - 1;
    constexpr int MI      = MT / 32;

    extern __shared__ char smem[];
    uint32_t sb = smem_u32(smem);

    const __half* Ah = (MODE == 0) ? g_xh : g_yh;
    const __half* Bw = (MODE == 0) ? g_wa : g_wp;

    float qsc = 1.0f;
    if (MODE == 0)
        qsc = sp[0] * (logf(2048.0f) * 0.125f) * 1.4426950408889634f;

    int tid = threadIdx.x;
    int lane = tid & 31;
    int wid = tid >> 5;
    int wm = wid >> 2;          // 0..1
    int wn = wid & 3;           // 0..3
    int m0 = blockIdx.y * MT;
    int n0 = blockIdx.x * 128;

    auto issue = [&](int it) {
        uint32_t dst0 = sb + (it % NST) * STAGE;
        int k0 = it * BK;
#pragma unroll
        for (int j = 0; j < (MT * 4) / 256; j++) {
            int c = tid + j * 256;
            int row = c >> 2;
            int seg = c & 3;
            uint32_t doff = SWZ64((uint32_t)(row * 64 + seg * 16));
            CP_ASYNC16(dst0 + doff, Ah + (size_t)(m0 + row) * K_ + k0 + seg * 8);
        }
#pragma unroll
        for (int j = 0; j < 2; j++) {
            int c = tid + j * 256;
            int row = c >> 2;
            int seg = c & 3;
            uint32_t doff = SWZ64((uint32_t)(row * 64 + seg * 16));
            CP_ASYNC16(dst0 + TILE_A + doff, Bw + (size_t)(n0 + row) * K_ + k0 + seg * 8);
        }
        CP_COMMIT();
    };

    float acc[MI][4][4];
#pragma unroll
    for (int mi = 0; mi < MI; mi++)
#pragma unroll
        for (int ni = 0; ni < 4; ni++)
#pragma unroll
            for (int q = 0; q < 4; q++) acc[mi][ni][q] = 0.0f;

#pragma unroll
    for (int i = 0; i < DEPTH; i++) issue(i);   // NIT=24 > DEPTH always

    int a_rowsel = (lane & 15);
    int a_half   = (lane >> 4) * 16;
    int b_rowsel = (lane & 7);
    int b_half   = ((lane >> 3) & 1) * 16;

    for (int it = 0; it < NIT; it++) {
        CP_WAIT(DEPTH - 1);                     // constant literal, no branches
        __syncthreads();
        if (it + DEPTH < NIT) issue(it + DEPTH);
        else                  CP_COMMIT();      // empty group keeps count exact

        uint32_t s0 = sb + (it % NST) * STAGE;
#pragma unroll
        for (int ks = 0; ks < 2; ks++) {
            uint32_t af[MI][4], bf[4][2];
#pragma unroll
            for (int mi = 0; mi < MI; mi++) {
                uint32_t lofs = (uint32_t)((wm * (MT / 2) + mi * 16 + a_rowsel) * 64
                                           + ks * 32 + a_half);
                ldsm_x4(af[mi], s0 + SWZ64(lofs));
            }
#pragma unroll
            for (int ni = 0; ni < 4; ni++) {
                uint32_t lofs = (uint32_t)((wn * 32 + ni * 8 + b_rowsel) * 64
                                           + ks * 32 + b_half);
                ldsm_x2(bf[ni], s0 + TILE_A + SWZ64(lofs));
            }
#pragma unroll
            for (int mi = 0; mi < MI; mi++)
#pragma unroll
                for (int ni = 0; ni < 4; ni++)
                    mma16816h(acc[mi][ni], af[mi], bf[ni]);
        }
    }
    __syncthreads();

    // Epilogue: stage C tile in smem, coalesced write
    float* stage = (float*)smem;   // [MT][132]
    int rq  = lane >> 2;
    int cp2 = (lane & 3) * 2;
#pragma unroll
    for (int mi = 0; mi < MI; mi++)
#pragma unroll
        for (int ni = 0; ni < 4; ni++) {
            int r = wm * (MT / 2) + mi * 16 + rq;
            int c = wn * 32 + ni * 8 + cp2;
            stage[r * 132 + c]           = acc[mi][ni][0];
            stage[r * 132 + c + 1]       = acc[mi][ni][1];
            stage[(r + 8) * 132 + c]     = acc[mi][ni][2];
            stage[(r + 8) * 132 + c + 1] = acc[mi][ni][3];
        }
    __syncthreads();

    constexpr int TPR = 256 / MT;          // threads per row (2 or 4)
    constexpr int CW  = 128 / TPR;         // floats per thread (64 or 32)
    int r = tid / TPR;
    int part = tid % TPR;
    const float* sr = stage + r * 132 + part * CW;

    if (MODE == 0) {
        // qkv scatter: q (scaled) / k / v single fp16
        int n = n0 + part * CW;
        int pt = n / 768;
        int w = n - pt * 768;
        int h = w >> 6;
        int m = m0 + r;
        int b = m >> 11;
        int t = m & 2047;
        size_t base = (((size_t)(b * H_ + h)) * T_ + t) * HD_;
        float sc = (pt == 0) ? qsc : 1.0f;
        __half* dst = (pt == 0) ? g_qh : (pt == 1) ? g_kh : g_vh;
        uint32_t hw[CW / 2];
#pragma unroll
        for (int i = 0; i < CW / 2; i++)
            hw[i] = f2h2(sr[2 * i] * sc, sr[2 * i + 1] * sc);
        uint4* ph = (uint4*)(dst + base);
#pragma unroll
        for (int q = 0; q < CW / 8; q++) ph[q] = ((uint4*)hw)[q];
    } else {
        float4* gp = (float4*)(Cout + (size_t)(m0 + r) * N + n0 + part * CW);
#pragma unroll
        for (int q = 0; q < CW / 4; q++) gp[q] = ((const float4*)sr)[q];
    }
}

// ---------------------------------------------------------------------------
// MMA flash attention, block-causal (block = 64 = k-tile), no online max.
// S: Q fp16 x K fp16. PV: fp16 x fp16. Row sums via ones-MMA (no scalar
// FADD chain, no shuffles). 6-stage K/V ring, constant-depth waits. 2 CTA/SM.
// ---------------------------------------------------------------------------
#define KV_TILE  (64 * 128)          // 8192
#define ASTG     (2 * KV_TILE)       // 16384 : K,V
#define NAST     6
#define ADEPTH   5
#define SM_ATT   (NAST * ASTG)       // 98304

__global__ __launch_bounds__(256, 2) void attn_mma()
{
    extern __shared__ char smem[];
    uint32_t sb = smem_u32(smem);
    int tid = threadIdx.x;
    int lane = tid & 31;
    int w = tid >> 5;

    int bh = blockIdx.x;
    int qt = 15 - blockIdx.y;

    const __half* Qh = g_qh + ((size_t)bh * T_ + qt * 128) * HD_;

    // ---- load Q tile, extract A-fragments ----
#pragma unroll
    for (int j = 0; j < 4; j++) {
        int idx = tid + j * 256;
        int row = idx >> 3;
        int seg = idx & 7;
        uint32_t doff = SWZ128((uint32_t)(row * 128 + seg * 16));
        size_t goff = (size_t)row * HD_ + seg * 8;
        CP_ASYNC16(sb + doff, Qh + goff);
    }
    CP_COMMIT();
    CP_WAIT(0);
    __syncthreads();

    uint32_t qh[4][4];
#pragma unroll
    for (int kb = 0; kb < 4; kb++) {
        uint32_t lofs = (uint32_t)((w * 16 + (lane & 15)) * 128 + kb * 32 + ((lane >> 4) & 1) * 16);
        ldsm_x4(qh[kb], sb + SWZ128(lofs));
    }
    __syncthreads();

    const __half* Kh = g_kh + (size_t)bh * T_ * HD_;
    const __half* Vh = g_vh + (size_t)bh * T_ * HD_;

    int nkt = 2 * qt + 2;
    int ktmax_w = 2 * qt + ((w >= 4) ? 1 : 0);

    auto issue = [&](int kt) {
        uint32_t d0 = sb + (kt % NAST) * ASTG;
        size_t g0 = (size_t)(kt * 64) * HD_;
#pragma unroll
        for (int j = 0; j < 2; j++) {
            int idx = tid + j * 256;
            int row = idx >> 3;
            int seg = idx & 7;
            uint32_t doff = SWZ128((uint32_t)(row * 128 + seg * 16));
            size_t goff = g0 + (size_t)row * HD_ + seg * 8;
            CP_ASYNC16(d0 + doff,           Kh + goff);
            CP_ASYNC16(d0 + KV_TILE + doff, Vh + goff);
        }
        CP_COMMIT();
    };

    // prologue: always ADEPTH commits (empty beyond nkt) so the constant
    // wait depth below is exact for any nkt
#pragma unroll
    for (int i = 0; i < ADEPTH; i++) {
        if (i < nkt) issue(i);
        else         CP_COMMIT();
    }

    // ones B-fragment: every element fp16 1.0 -> MMA with P gives row sums
    const uint32_t b_ones[2] = { 0x3C003C00u, 0x3C003C00u };

    float oacc[8][4];
#pragma unroll
    for (int j = 0; j < 8; j++)
#pragma unroll
        for (int q = 0; q < 4; q++) oacc[j][q] = 0.0f;
    float lacc[4] = {0.f, 0.f, 0.f, 0.f};

    for (int kt = 0; kt < nkt; kt++) {
        CP_WAIT(ADEPTH - 1);                 // constant literal
        __syncthreads();
        if (kt + ADEPTH < nkt) issue(kt + ADEPTH);
        else                   CP_COMMIT();

        if (kt <= ktmax_w) {
            uint32_t base = sb + (kt % NAST) * ASTG;

            // ---- S = Q @ K^T ----
            float sacc[8][4];
#pragma unroll
            for (int j = 0; j < 8; j++)
#pragma unroll
                for (int q = 0; q < 4; q++) sacc[j][q] = 0.0f;

#pragma unroll
            for (int jj = 0; jj < 4; jj++) {
#pragma unroll
                for (int kb = 0; kb < 4; kb++) {
                    uint32_t khf[4];
                    uint32_t lofs = (uint32_t)(
                        (jj * 16 + (lane & 7) + ((lane >> 4) & 1) * 8) * 128
                        + kb * 32 + ((lane >> 3) & 1) * 16);
                    ldsm_x4(khf, base + SWZ128(lofs));
                    mma16816h(sacc[2 * jj],     qh[kb], khf + 0);
                    mma16816h(sacc[2 * jj + 1], qh[kb], khf + 2);
                }
            }

            // ---- p = exp2(S) ----
#pragma unroll
            for (int j = 0; j < 8; j++) {
                sacc[j][0] = ex2f(sacc[j][0]);
                sacc[j][1] = ex2f(sacc[j][1]);
                sacc[j][2] = ex2f(sacc[j][2]);
                sacc[j][3] = ex2f(sacc[j][3]);
            }

            // ---- O += P @ V ; rowsum += P @ ones (tensor-core reduction) ----
#pragma unroll
            for (int kb = 0; kb < 4; kb++) {
                uint32_t pa[4];
                int j0 = 2 * kb, j1 = 2 * kb + 1;
                pa[0] = f2h2(sacc[j0][0], sacc[j0][1]);
                pa[1] = f2h2(sacc[j0][2], sacc[j0][3]);
                pa[2] = f2h2(sacc[j1][0], sacc[j1][1]);
                pa[3] = f2h2(sacc[j1][2], sacc[j1][3]);
                mma16816h(lacc, pa, b_ones);
#pragma unroll
                for (int dd = 0; dd < 4; dd++) {
                    uint32_t vhf[4];
                    uint32_t lofs = (uint32_t)(
                        (kb * 16 + (lane & 15)) * 128
                        + dd * 32 + ((lane >> 4) & 1) * 16);
                    ldsm_x4_t(vhf, base + KV_TILE + SWZ128(lofs));
                    mma16816h(oacc[2 * dd],     pa, vhf + 0);
                    mma16816h(oacc[2 * dd + 1], pa, vhf + 2);
                }
            }
        }
    }
    __syncthreads();

    // ---- epilogue: normalize (l from ones-MMA), stage, write y fp16 ----
    float inv0 = 1.0f / lacc[0], inv1 = 1.0f / lacc[2];
    float* st = (float*)smem;                 // [128][68]
    int r0 = w * 16 + (lane >> 2);
    int cb = (lane & 3) * 2;
#pragma unroll
    for (int j = 0; j < 8; j++) {
        st[r0 * 68 + j * 8 + cb]           = oacc[j][0] * inv0;
        st[r0 * 68 + j * 8 + cb + 1]       = oacc[j][1] * inv0;
        st[(r0 + 8) * 68 + j * 8 + cb]     = oacc[j][2] * inv1;
        st[(r0 + 8) * 68 + j * 8 + cb + 1] = oacc[j][3] * inv1;
    }
    __syncthreads();

    int row = tid >> 1;
    int hf = tid & 1;
    int b = bh / H_;
    int h = bh - b * H_;
    int t = qt * 128 + row;
    size_t ybase = ((size_t)(b * T_ + t)) * C_ + h * HD_ + hf * 32;
    const float* srow = st + row * 68 + hf * 32;
    uint32_t hw[16];
#pragma unroll
    for (int i = 0; i < 16; i++)
        hw[i] = f2h2(srow[2 * i], srow[2 * i + 1]);
    uint4* ph = (uint4*)(g_yh + ybase);
#pragma unroll
    for (int q = 0; q < 4; q++) ph[q] = ((uint4*)hw)[q];
}

// ---------------------------------------------------------------------------
extern "C" void kernel_launch(void* const* d_in, const int* in_sizes, int n_in,
                              void* d_out, int out_size)
{
    const float* x     = (const float*)d_in[0];
    const float* wattn = (const float*)d_in[1];
    const float* wproj = (const float*)d_in[2];
    const float* s     = (const float*)d_in[3];
    float* out = (float*)d_out;

    // 0) x, weights -> single fp16
    int tot4 = (M_ * K_ + N_QKV * K_ + C_ * C_) / 4;
    convert_kernel<<<(tot4 + 255) / 256, 256>>>(x, wattn, wproj);

    const int SM_G0 = 6 * (128 * 64 + 128 * 64);   // 98304
    const int SM_G1 = 8 * (64 * 64 + 128 * 64);    // 98304
    cudaFuncSetAttribute((const void*)tcgemm<128, 0>,
                         cudaFuncAttributeMaxDynamicSharedMemorySize, SM_G0);
    cudaFuncSetAttribute((const void*)tcgemm<64, 1>,
                         cudaFuncAttributeMaxDynamicSharedMemorySize, SM_G1);
    cudaFuncSetAttribute((const void*)attn_mma,
                         cudaFuncAttributeMaxDynamicSharedMemorySize, SM_ATT);

    // 1) qkv projection (1-product fp16): q (pre-scaled) / k / v fp16
    tcgemm<128, 0><<<dim3(N_QKV / 128, M_ / 128), 256, SM_G0>>>(nullptr, s, N_QKV);

    // 2) MMA flash attention (writes y single fp16)
    attn_mma<<<dim3(B_ * H_, T_ / 128), 256, SM_ATT>>>();

    // 3) output projection (1-product, 64-row tiles, 8-stage ring)
    tcgemm<64, 1><<<dim3(C_ / 128, M_ / 64), 256, SM_G1>>>(out, nullptr, C_);
}

// round 17
// speedup vs baseline: 1.2588x; 1.0265x over previous
#include <cuda_runtime.h>
#include <cuda_bf16.h>
#include <cuda_fp16.h>
#include <math.h>
#include <stdint.h>

// Problem constants
#define B_    2
#define T_    2048
#define C_    768
#define H_    12
#define HD_   64
#define M_    4096
#define K_    768
#define N_QKV 2304

// ---------------------------------------------------------------------------
// Scratch (allocation-free: __device__ globals) — fp16 everywhere
// ---------------------------------------------------------------------------
__device__ alignas(16) __half g_qh[B_ * H_ * T_ * HD_];   // pre-scaled
__device__ alignas(16) __half g_kh[B_ * H_ * T_ * HD_];
__device__ alignas(16) __half g_vh[B_ * H_ * T_ * HD_];

__device__ alignas(16) __half g_xh[M_ * K_];
__device__ alignas(16) __half g_wa[N_QKV * K_];
__device__ alignas(16) __half g_wp[C_ * C_];
__device__ alignas(16) __half g_yh[M_ * C_];

// ---------------------------------------------------------------------------
// PTX helpers
// ---------------------------------------------------------------------------
__device__ __forceinline__ uint32_t smem_u32(const void* p) {
    uint32_t a;
    asm("{ .reg .u64 t; cvta.to.shared.u64 t, %1; cvt.u32.u64 %0, t; }" : "=r"(a) : "l"(p));
    return a;
}
__device__ __forceinline__ void ldsm_x4(uint32_t* r, uint32_t addr) {
    asm volatile("ldmatrix.sync.aligned.m8n8.x4.shared.b16 {%0,%1,%2,%3}, [%4];"
                 : "=r"(r[0]), "=r"(r[1]), "=r"(r[2]), "=r"(r[3]) : "r"(addr));
}
__device__ __forceinline__ void ldsm_x4_t(uint32_t* r, uint32_t addr) {
    asm volatile("ldmatrix.sync.aligned.m8n8.x4.trans.shared.b16 {%0,%1,%2,%3}, [%4];"
                 : "=r"(r[0]), "=r"(r[1]), "=r"(r[2]), "=r"(r[3]) : "r"(addr));
}
__device__ __forceinline__ void ldsm_x2(uint32_t* r, uint32_t addr) {
    asm volatile("ldmatrix.sync.aligned.m8n8.x2.shared.b16 {%0,%1}, [%2];"
                 : "=r"(r[0]), "=r"(r[1]) : "r"(addr));
}
__device__ __forceinline__ void mma16816h(float* c, const uint32_t* a, const uint32_t* b) {
    asm volatile("mma.sync.aligned.m16n8k16.row.col.f32.f16.f16.f32 "
                 "{%0,%1,%2,%3}, {%4,%5,%6,%7}, {%8,%9}, {%0,%1,%2,%3};"
                 : "+f"(c[0]), "+f"(c[1]), "+f"(c[2]), "+f"(c[3])
                 : "r"(a[0]), "r"(a[1]), "r"(a[2]), "r"(a[3]), "r"(b[0]), "r"(b[1]));
}
__device__ __forceinline__ float ex2f(float x) {
    float y; asm("ex2.approx.f32 %0, %1;" : "=f"(y) : "f"(x)); return y;
}
__device__ __forceinline__ uint32_t f2h2(float a, float b) {
    __half2 h = __floats2half2_rn(a, b);
    return *reinterpret_cast<uint32_t*>(&h);
}
#define CP_ASYNC16(dst, src) \
    asm volatile("cp.async.cg.shared.global [%0], [%1], 16;" :: "r"(dst), "l"(src) : "memory")
#define CP_COMMIT() asm volatile("cp.async.commit_group;" ::: "memory")
#define CP_WAIT(n)  asm volatile("cp.async.wait_group %0;" :: "n"(n) : "memory")

#define SWZ64(o)  ((o) ^ (((o) >> 3) & 0x30))
#define SWZ128(o) ((o) ^ (((o) >> 3) & 0x70))

// ---------------------------------------------------------------------------
// Conversion: x, wa, wp -> single fp16
// ---------------------------------------------------------------------------
__global__ __launch_bounds__(256) void convert_kernel(
    const float* __restrict__ x, const float* __restrict__ wa, const float* __restrict__ wp)
{
    const int nx = M_ * K_ / 4, na = N_QKV * K_ / 4, np = C_ * C_ / 4;
    int idx = blockIdx.x * blockDim.x + threadIdx.x;
    const float* src; __half* dst; int l;
    if (idx < nx)                { src = x;  dst = g_xh; l = idx; }
    else if (idx < nx + na)      { src = wa; dst = g_wa; l = idx - nx; }
    else if (idx < nx + na + np) { src = wp; dst = g_wp; l = idx - nx - na; }
    else return;

    float4 v = ((const float4*)src)[l];
    uint32_t h2[2] = { f2h2(v.x, v.y), f2h2(v.z, v.w) };
    ((uint2*)dst)[l] = *(uint2*)h2;
}

// ---------------------------------------------------------------------------
// Templated tensor-core GEMM: C[M,N] = A[M,K] @ Bw[N,K]^T, fp16 x fp16 (1 prod).
// MODE 0: MT=128, A=g_xh, B=g_wa -> scatter q(scaled)/k/v fp16, 6-stage ring.
// MODE 1: MT=64,  A=g_yh, B=g_wp -> fp32 row-major Cout, 8-stage ring.
// 2-iteration super-steps: one wait+sync per two K-chunks. 2 CTA/SM.
// ---------------------------------------------------------------------------
#define BK      32
#define NIT     (K_ / BK)           // 24

template<int MT, int MODE>
__global__ __launch_bounds__(256, 2)
void tcgemm(float* __restrict__ Cout, const float* __restrict__ sp, int N)
{
    constexpr int TILE_A  = MT * 64;            // A tile bytes
    constexpr int TILE_Bb = 128 * 64;           // B tile bytes
    constexpr int STAGE   = TILE_A + TILE_Bb;
    constexpr int NST     = (MT == 128) ? 6 : 8;
    constexpr int PRE     = NST - 2;            // prologue stages (even)
    constexpr int NSUP    = NIT / 2;            // 12

    constexpr int MI      = MT / 32;

    extern __shared__ char smem[];
    uint32_t sb = smem_u32(smem);

    const __half* Ah = (MODE == 0) ? g_xh : g_yh;
    const __half* Bw = (MODE == 0) ? g_wa : g_wp;

    float qsc = 1.0f;
    if (MODE == 0)
        qsc = sp[0] * (logf(2048.0f) * 0.125f) * 1.4426950408889634f;

    int tid = threadIdx.x;
    int lane = tid & 31;
    int wid = tid >> 5;
    int wm = wid >> 2;          // 0..1
    int wn = wid & 3;           // 0..3
    int m0 = blockIdx.y * MT;
    int n0 = blockIdx.x * 128;

    auto issue = [&](int it) {
        uint32_t dst0 = sb + (it % NST) * STAGE;
        int k0 = it * BK;
#pragma unroll
        for (int j = 0; j < (MT * 4) / 256; j++) {
            int c = tid + j * 256;
            int row = c >> 2;
            int seg = c & 3;
            uint32_t doff = SWZ64((uint32_t)(row * 64 + seg * 16));
            CP_ASYNC16(dst0 + doff, Ah + (size_t)(m0 + row) * K_ + k0 + seg * 8);
        }
#pragma unroll
        for (int j = 0; j < 2; j++) {
            int c = tid + j * 256;
            int row = c >> 2;
            int seg = c & 3;
            uint32_t doff = SWZ64((uint32_t)(row * 64 + seg * 16));
            CP_ASYNC16(dst0 + TILE_A + doff, Bw + (size_t)(n0 + row) * K_ + k0 + seg * 8);
        }
        CP_COMMIT();
    };

    float acc[MI][4][4];
#pragma unroll
    for (int mi = 0; mi < MI; mi++)
#pragma unroll
        for (int ni = 0; ni < 4; ni++)
#pragma unroll
            for (int q = 0; q < 4; q++) acc[mi][ni][q] = 0.0f;

#pragma unroll
    for (int i = 0; i < PRE; i++) issue(i);     // NIT=24 > PRE always

    int a_rowsel = (lane & 15);
    int a_half   = (lane >> 4) * 16;
    int b_rowsel = (lane & 7);
    int b_half   = ((lane >> 3) & 1) * 16;

    auto compute = [&](int it) {
        uint32_t s0 = sb + (it % NST) * STAGE;
#pragma unroll
        for (int ks = 0; ks < 2; ks++) {
            uint32_t af[MI][4], bf[4][2];
#pragma unroll
            for (int mi = 0; mi < MI; mi++) {
                uint32_t lofs = (uint32_t)((wm * (MT / 2) + mi * 16 + a_rowsel) * 64
                                           + ks * 32 + a_half);
                ldsm_x4(af[mi], s0 + SWZ64(lofs));
            }
#pragma unroll
            for (int ni = 0; ni < 4; ni++) {
                uint32_t lofs = (uint32_t)((wn * 32 + ni * 8 + b_rowsel) * 64
                                           + ks * 32 + b_half);
                ldsm_x2(bf[ni], s0 + TILE_A + SWZ64(lofs));
            }
#pragma unroll
            for (int mi = 0; mi < MI; mi++)
#pragma unroll
                for (int ni = 0; ni < 4; ni++)
                    mma16816h(acc[mi][ni], af[mi], bf[ni]);
        }
    };

    for (int si = 0; si < NSUP; si++) {
        int kt0 = 2 * si;
        CP_WAIT(NST - 4);                       // oldest 2 groups complete
        __syncthreads();
        if (kt0 + PRE     < NIT) issue(kt0 + PRE);     else CP_COMMIT();
        if (kt0 + PRE + 1 < NIT) issue(kt0 + PRE + 1); else CP_COMMIT();
        compute(kt0);
        compute(kt0 + 1);
    }
    __syncthreads();

    // Epilogue: stage C tile in smem, coalesced write
    float* stage = (float*)smem;   // [MT][132]
    int rq  = lane >> 2;
    int cp2 = (lane & 3) * 2;
#pragma unroll
    for (int mi = 0; mi < MI; mi++)
#pragma unroll
        for (int ni = 0; ni < 4; ni++) {
            int r = wm * (MT / 2) + mi * 16 + rq;
            int c = wn * 32 + ni * 8 + cp2;
            stage[r * 132 + c]           = acc[mi][ni][0];
            stage[r * 132 + c + 1]       = acc[mi][ni][1];
            stage[(r + 8) * 132 + c]     = acc[mi][ni][2];
            stage[(r + 8) * 132 + c + 1] = acc[mi][ni][3];
        }
    __syncthreads();

    constexpr int TPR = 256 / MT;          // threads per row (2 or 4)
    constexpr int CW  = 128 / TPR;         // floats per thread (64 or 32)
    int r = tid / TPR;
    int part = tid % TPR;
    const float* sr = stage + r * 132 + part * CW;

    if (MODE == 0) {
        // qkv scatter: q (scaled) / k / v single fp16
        int n = n0 + part * CW;
        int pt = n / 768;
        int w = n - pt * 768;
        int h = w >> 6;
        int m = m0 + r;
        int b = m >> 11;
        int t = m & 2047;
        size_t base = (((size_t)(b * H_ + h)) * T_ + t) * HD_;
        float sc = (pt == 0) ? qsc : 1.0f;
        __half* dst = (pt == 0) ? g_qh : (pt == 1) ? g_kh : g_vh;
        uint32_t hw[CW / 2];
#pragma unroll
        for (int i = 0; i < CW / 2; i++)
            hw[i] = f2h2(sr[2 * i] * sc, sr[2 * i + 1] * sc);
        uint4* ph = (uint4*)(dst + base);
#pragma unroll
        for (int q = 0; q < CW / 8; q++) ph[q] = ((uint4*)hw)[q];
    } else {
        float4* gp = (float4*)(Cout + (size_t)(m0 + r) * N + n0 + part * CW);
#pragma unroll
        for (int q = 0; q < CW / 4; q++) gp[q] = ((const float4*)sr)[q];
    }
}

// ---------------------------------------------------------------------------
// MMA flash attention, block-causal (block = 64 = k-tile), no online max.
// S: Q fp16 x K fp16. PV: fp16 x fp16. Row sums via ones-MMA.
// 6-stage K/V ring, 2-tile super-iterations (nkt always even). 2 CTA/SM.
// ---------------------------------------------------------------------------
#define KV_TILE  (64 * 128)          // 8192
#define ASTG     (2 * KV_TILE)       // 16384 : K,V
#define NAST     6
#define SM_ATT   (NAST * ASTG)       // 98304

__global__ __launch_bounds__(256, 2) void attn_mma()
{
    extern __shared__ char smem[];
    uint32_t sb = smem_u32(smem);
    int tid = threadIdx.x;
    int lane = tid & 31;
    int w = tid >> 5;

    int bh = blockIdx.x;
    int qt = 15 - blockIdx.y;

    const __half* Qh = g_qh + ((size_t)bh * T_ + qt * 128) * HD_;

    // ---- load Q tile, extract A-fragments ----
#pragma unroll
    for (int j = 0; j < 4; j++) {
        int idx = tid + j * 256;
        int row = idx >> 3;
        int seg = idx & 7;
        uint32_t doff = SWZ128((uint32_t)(row * 128 + seg * 16));
        size_t goff = (size_t)row * HD_ + seg * 8;
        CP_ASYNC16(sb + doff, Qh + goff);
    }
    CP_COMMIT();
    CP_WAIT(0);
    __syncthreads();

    uint32_t qh[4][4];
#pragma unroll
    for (int kb = 0; kb < 4; kb++) {
        uint32_t lofs = (uint32_t)((w * 16 + (lane & 15)) * 128 + kb * 32 + ((lane >> 4) & 1) * 16);
        ldsm_x4(qh[kb], sb + SWZ128(lofs));
    }
    __syncthreads();

    const __half* Kh = g_kh + (size_t)bh * T_ * HD_;
    const __half* Vh = g_vh + (size_t)bh * T_ * HD_;

    int nkt = 2 * qt + 2;                 // always even
    int nsuper = qt + 1;

    auto issue = [&](int kt) {
        uint32_t d0 = sb + (kt % NAST) * ASTG;
        size_t g0 = (size_t)(kt * 64) * HD_;
#pragma unroll
        for (int j = 0; j < 2; j++) {
            int idx = tid + j * 256;
            int row = idx >> 3;
            int seg = idx & 7;
            uint32_t doff = SWZ128((uint32_t)(row * 128 + seg * 16));
            size_t goff = g0 + (size_t)row * HD_ + seg * 8;
            CP_ASYNC16(d0 + doff,           Kh + goff);
            CP_ASYNC16(d0 + KV_TILE + doff, Vh + goff);
        }
        CP_COMMIT();
    };

    // prologue: exactly 4 commits (empty beyond nkt) -> 4 groups outstanding
#pragma unroll
    for (int i = 0; i < 4; i++) {
        if (i < nkt) issue(i);
        else         CP_COMMIT();
    }

    // ones B-fragment: every element fp16 1.0 -> MMA with P gives row sums
    const uint32_t b_ones[2] = { 0x3C003C00u, 0x3C003C00u };

    float oacc[8][4];
#pragma unroll
    for (int j = 0; j < 8; j++)
#pragma unroll
        for (int q = 0; q < 4; q++) oacc[j][q] = 0.0f;
    float lacc[4] = {0.f, 0.f, 0.f, 0.f};

    auto compute = [&](int kt) {
        uint32_t base = sb + (kt % NAST) * ASTG;

        // ---- S = Q @ K^T ----
        float sacc[8][4];
#pragma unroll
        for (int j = 0; j < 8; j++)
#pragma unroll
            for (int q = 0; q < 4; q++) sacc[j][q] = 0.0f;

#pragma unroll
        for (int jj = 0; jj < 4; jj++) {
#pragma unroll
            for (int kb = 0; kb < 4; kb++) {
                uint32_t khf[4];
                uint32_t lofs = (uint32_t)(
                    (jj * 16 + (lane & 7) + ((lane >> 4) & 1) * 8) * 128
                    + kb * 32 + ((lane >> 3) & 1) * 16);
                ldsm_x4(khf, base + SWZ128(lofs));
                mma16816h(sacc[2 * jj],     qh[kb], khf + 0);
                mma16816h(sacc[2 * jj + 1], qh[kb], khf + 2);
            }
        }

        // ---- p = exp2(S) ----
#pragma unroll
        for (int j = 0; j < 8; j++) {
            sacc[j][0] = ex2f(sacc[j][0]);
            sacc[j][1] = ex2f(sacc[j][1]);
            sacc[j][2] = ex2f(sacc[j][2]);
            sacc[j][3] = ex2f(sacc[j][3]);
        }

        // ---- O += P @ V ; rowsum += P @ ones ----
#pragma unroll
        for (int kb = 0; kb < 4; kb++) {
            uint32_t pa[4];
            int j0 = 2 * kb, j1 = 2 * kb + 1;
            pa[0] = f2h2(sacc[j0][0], sacc[j0][1]);
            pa[1] = f2h2(sacc[j0][2], sacc[j0][3]);
            pa[2] = f2h2(sacc[j1][0], sacc[j1][1]);
            pa[3] = f2h2(sacc[j1][2], sacc[j1][3]);
            mma16816h(lacc, pa, b_ones);
#pragma unroll
            for (int dd = 0; dd < 4; dd++) {
                uint32_t vhf[4];
                uint32_t lofs = (uint32_t)(
                    (kb * 16 + (lane & 15)) * 128
                    + dd * 32 + ((lane >> 4) & 1) * 16);
                ldsm_x4_t(vhf, base + KV_TILE + SWZ128(lofs));
                mma16816h(oacc[2 * dd],     pa, vhf + 0);
                mma16816h(oacc[2 * dd + 1], pa, vhf + 2);
            }
        }
    };

    for (int si = 0; si < nsuper; si++) {
        int kt0 = 2 * si;
        CP_WAIT(2);                       // oldest 2 groups (kt0, kt0+1) ready
        __syncthreads();
        if (kt0 + 4 < nkt) issue(kt0 + 4); else CP_COMMIT();
        if (kt0 + 5 < nkt) issue(kt0 + 5); else CP_COMMIT();

        compute(kt0);                     // always valid for every warp
        if (si + 1 < nsuper || w >= 4)    // block-causal: last pair's 2nd tile
            compute(kt0 + 1);             // only for lower-half q warps
    }
    __syncthreads();

    // ---- epilogue: normalize (l from ones-MMA), stage, write y fp16 ----
    float inv0 = 1.0f / lacc[0], inv1 = 1.0f / lacc[2];
    float* st = (float*)smem;                 // [128][68]
    int r0 = w * 16 + (lane >> 2);
    int cb = (lane & 3) * 2;
#pragma unroll
    for (int j = 0; j < 8; j++) {
        st[r0 * 68 + j * 8 + cb]           = oacc[j][0] * inv0;
        st[r0 * 68 + j * 8 + cb + 1]       = oacc[j][1] * inv0;
        st[(r0 + 8) * 68 + j * 8 + cb]     = oacc[j][2] * inv1;
        st[(r0 + 8) * 68 + j * 8 + cb + 1] = oacc[j][3] * inv1;
    }
    __syncthreads();

    int row = tid >> 1;
    int hf = tid & 1;
    int b = bh / H_;
    int h = bh - b * H_;
    int t = qt * 128 + row;
    size_t ybase = ((size_t)(b * T_ + t)) * C_ + h * HD_ + hf * 32;
    const float* srow = st + row * 68 + hf * 32;
    uint32_t hw[16];
#pragma unroll
    for (int i = 0; i < 16; i++)
        hw[i] = f2h2(srow[2 * i], srow[2 * i + 1]);
    uint4* ph = (uint4*)(g_yh + ybase);
#pragma unroll
    for (int q = 0; q < 4; q++) ph[q] = ((uint4*)hw)[q];
}

// ---------------------------------------------------------------------------
extern "C" void kernel_launch(void* const* d_in, const int* in_sizes, int n_in,
                              void* d_out, int out_size)
{
    const float* x     = (const float*)d_in[0];
    const float* wattn = (const float*)d_in[1];
    const float* wproj = (const float*)d_in[2];
    const float* s     = (const float*)d_in[3];
    float* out = (float*)d_out;

    // 0) x, weights -> single fp16
    int tot4 = (M_ * K_ + N_QKV * K_ + C_ * C_) / 4;
    convert_kernel<<<(tot4 + 255) / 256, 256>>>(x, wattn, wproj);

    const int SM_G0 = 6 * (128 * 64 + 128 * 64);   // 98304
    const int SM_G1 = 8 * (64 * 64 + 128 * 64);    // 98304
    cudaFuncSetAttribute((const void*)tcgemm<128, 0>,
                         cudaFuncAttributeMaxDynamicSharedMemorySize, SM_G0);
    cudaFuncSetAttribute((const void*)tcgemm<64, 1>,
                         cudaFuncAttributeMaxDynamicSharedMemorySize, SM_G1);
    cudaFuncSetAttribute((const void*)attn_mma,
                         cudaFuncAttributeMaxDynamicSharedMemorySize, SM_ATT);

    // 1) qkv projection (1-product fp16): q (pre-scaled) / k / v fp16
    tcgemm<128, 0><<<dim3(N_QKV / 128, M_ / 128), 256, SM_G0>>>(nullptr, s, N_QKV);

    // 2) MMA flash attention (writes y single fp16)
    attn_mma<<<dim3(B_ * H_, T_ / 128), 256, SM_ATT>>>();

    // 3) output projection (1-product, 64-row tiles, 8-stage ring)
    tcgemm<64, 1><<<dim3(C_ / 128, M_ / 64), 256, SM_G1>>>(out, nullptr, C_);
}